// round 3
// baseline (speedup 1.0000x reference)
#include <cuda_runtime.h>

#define NN   100000
#define DD   64
#define EE   400000
#define LV   4
#define ELV  (EE/LV)
#define NLF  10000
#define G3   192
#define SS   68   // padded shared stride

// ---------------- scratch (device globals; no runtime allocation) ----------
__device__ float g_gi[2][(size_t)NN*G3];   // x@Wih^T + bih, per graph
__device__ float g_msg[2][(size_t)NN*DD];  // attention-weighted message
__device__ float g_lq[2][NN];              // x . wa_q
__device__ float g_lh[2][NN];              // h . wa_k (per level)
__device__ int   g_mx[2][NN];              // segment max (ordered-int float)
__device__ float g_den[2][NN];             // softmax denominator
__device__ float g_le[2][EE];              // edge_attr . (We^T wa_k) + be.wa_k
__device__ float g_ex[2][EE];              // logit, then exp numerator
__device__ int   g_in[2][NN];              // has incoming edge
__device__ int   g_list[2][NN];            // compacted receiving nodes
__device__ int   g_cnt[2];
__device__ float g_v[DD];                  // We^T wa_k
__device__ float g_c[1];                   // be . wa_k
__device__ float g_WcT[128*128];           // Wc transposed

// ---------------- helpers ---------------------------------------------------
__device__ __forceinline__ int f2o(float f){ int i=__float_as_int(f); return i>=0?i:(i^0x7fffffff); }
__device__ __forceinline__ float o2f(int i){ return __int_as_float(i>=0?i:(i^0x7fffffff)); }
__device__ __forceinline__ float wredsum(float v){
    #pragma unroll
    for(int o=16;o;o>>=1) v += __shfl_down_sync(0xffffffffu, v, o);
    return v;
}
__device__ __forceinline__ float sigf(float x){ return 1.f/(1.f+__expf(-x)); }

// ---------------- tiny precompute -------------------------------------------
__global__ void k_small(const float* We, const float* Wa, const float* be, const float* Wc){
    int t = threadIdx.x;
    if(t < DD){
        float s = 0.f;
        for(int j=0;j<DD;j++) s += Wa[DD+j]*We[j*DD+t];
        g_v[t] = s;
    }
    if(t == DD){
        float s = 0.f;
        for(int j=0;j<DD;j++) s += be[j]*Wa[DD+j];
        g_c[0] = s;
    }
    for(int i=t;i<128*128;i+=blockDim.x){
        int j=i/128, k=i%128;
        g_WcT[k*128+j] = Wc[i];
    }
}

// ---------------- node init: lq, clear in-flag --------------------------------
__global__ void k_node_init(const float* x1, const float* x2, const float* Wa){
    int g = blockIdx.y;
    int n = blockIdx.x*8 + (threadIdx.x>>5);
    if(n >= NN) return;
    int lane = threadIdx.x & 31;
    const float* x = g ? x2 : x1;
    float v = x[(size_t)n*DD+lane]*Wa[lane] + x[(size_t)n*DD+32+lane]*Wa[32+lane];
    v = wredsum(v);
    if(lane==0){
        g_lq[g][n] = v;
        g_in[g][n] = 0;
    }
}

// ---------------- edge init: le, incoming flags --------------------------------
__global__ void k_edge_init(const float* ea1, const float* ea2,
                            const int* ei1, const int* ei2){
    int g = blockIdx.y;
    int e = blockIdx.x*8 + (threadIdx.x>>5);
    if(e >= EE) return;
    int lane = threadIdx.x & 31;
    const float* ea = g ? ea2 : ea1;
    const int*   ei = g ? ei2 : ei1;
    float v = ea[(size_t)e*DD+lane]*g_v[lane] + ea[(size_t)e*DD+32+lane]*g_v[32+lane];
    v = wredsum(v);
    if(lane==0){
        g_le[g][e] = v + g_c[0];
        g_in[g][ei[EE+e]] = 1;  // dst has incoming edge
    }
}

// ---------------- gi GEMM + fused root h0 ------------------------------------
__global__ __launch_bounds__(256) void k_gemm_gi(const float* x1, const float* x2,
        const float* Wih, const float* bih, const float* bhh,
        float* o1, float* o2){
    __shared__ float xs[64*SS];
    __shared__ float ws[64*SS];
    int g = blockIdx.y;
    const float* x = g ? x2 : x1;
    float* h = g ? o2 : o1;
    int t = threadIdx.x;
    int base = blockIdx.x*64;

    // load x tile transposed: xs[k][row]
    #pragma unroll
    for(int i=0;i<4;i++){
        int idx = t + i*256;
        int r = idx>>4, c4 = (idx&15)*4;
        int n = base + r;
        float4 v = make_float4(0.f,0.f,0.f,0.f);
        if(n < NN) v = *(const float4*)&x[(size_t)n*DD + c4];
        xs[(c4+0)*SS + r] = v.x;
        xs[(c4+1)*SS + r] = v.y;
        xs[(c4+2)*SS + r] = v.z;
        xs[(c4+3)*SS + r] = v.w;
    }
    int n0 = (t&15)*4, j0 = (t>>4)*4;
    float acc[3][16];
    #pragma unroll
    for(int p=0;p<3;p++){
        __syncthreads();
        #pragma unroll
        for(int i=0;i<4;i++){
            int idx = t + i*256;
            int r = idx>>4, c4 = (idx&15)*4;
            float4 v = *(const float4*)&Wih[(size_t)(p*64 + r)*DD + c4];
            ws[(c4+0)*SS + r] = v.x;
            ws[(c4+1)*SS + r] = v.y;
            ws[(c4+2)*SS + r] = v.z;
            ws[(c4+3)*SS + r] = v.w;
        }
        __syncthreads();
        #pragma unroll
        for(int q=0;q<16;q++) acc[p][q] = 0.f;
        #pragma unroll 8
        for(int k=0;k<64;k++){
            float4 xv = *(float4*)&xs[k*SS + n0];
            float4 wv = *(float4*)&ws[k*SS + j0];
            acc[p][0] += xv.x*wv.x; acc[p][1] += xv.x*wv.y; acc[p][2] += xv.x*wv.z; acc[p][3] += xv.x*wv.w;
            acc[p][4] += xv.y*wv.x; acc[p][5] += xv.y*wv.y; acc[p][6] += xv.y*wv.z; acc[p][7] += xv.y*wv.w;
            acc[p][8] += xv.z*wv.x; acc[p][9] += xv.z*wv.y; acc[p][10]+= xv.z*wv.z; acc[p][11]+= xv.z*wv.w;
            acc[p][12]+= xv.w*wv.x; acc[p][13]+= xv.w*wv.y; acc[p][14]+= xv.w*wv.z; acc[p][15]+= xv.w*wv.w;
        }
    }
    // epilogue: write gi (incl. bih), compute h0 = (1-z)*n for roots, 0 otherwise
    #pragma unroll
    for(int ni=0;ni<4;ni++){
        int n = base + n0 + ni;
        if(n >= NN) continue;
        bool root = (g_in[g][n] == 0);
        float gvals[12];
        #pragma unroll
        for(int p=0;p<3;p++){
            #pragma unroll
            for(int ji=0;ji<4;ji++)
                gvals[p*4+ji] = acc[p][ni*4+ji] + __ldg(&bih[p*64 + j0 + ji]);
            float4 st = make_float4(gvals[p*4],gvals[p*4+1],gvals[p*4+2],gvals[p*4+3]);
            *(float4*)&g_gi[g][(size_t)n*G3 + p*64 + j0] = st;
        }
        float hv[4];
        #pragma unroll
        for(int ji=0;ji<4;ji++){
            int d = j0 + ji;
            float r  = sigf(gvals[ji]   + __ldg(&bhh[d]));
            float z  = sigf(gvals[4+ji] + __ldg(&bhh[64+d]));
            float nn = tanhf(gvals[8+ji] + r*__ldg(&bhh[128+d]));
            hv[ji] = root ? (1.f - z)*nn : 0.f;
        }
        *(float4*)&h[(size_t)n*DD + j0] = make_float4(hv[0],hv[1],hv[2],hv[3]);
    }
}

// ---------------- per-level prep: lh, clear mx/den/msg, reset counter --------
__global__ void k_prep(const float* Wa, const float* o1, const float* o2){
    if(blockIdx.y==0 && blockIdx.x==0 && threadIdx.x==0){ g_cnt[0]=0; g_cnt[1]=0; }
    int g = blockIdx.y;
    int n = blockIdx.x*8 + (threadIdx.x>>5);
    if(n >= NN) return;
    int lane = threadIdx.x & 31;
    const float* h = g ? o2 : o1;
    float v = h[(size_t)n*DD+lane]*Wa[DD+lane] + h[(size_t)n*DD+32+lane]*Wa[96+lane];
    v = wredsum(v);
    if(lane==0){
        g_lh[g][n] = v;
        g_mx[g][n] = f2o(-1e30f);
        g_den[g][n] = 0.f;
    }
    g_msg[g][(size_t)n*DD+lane]    = 0.f;
    g_msg[g][(size_t)n*DD+32+lane] = 0.f;
}

// ---------------- logits + segment max ---------------------------------------
__global__ void k_logit(const int* ei1, const int* ei2, const float* ba, int l){
    int g = blockIdx.y;
    int el = blockIdx.x*256 + threadIdx.x;
    if(el >= ELV) return;
    int e = el*LV + l;
    const int* ei = g ? ei2 : ei1;
    int s = ei[e], d = ei[EE+e];
    float lg = g_lq[g][d] + g_lh[g][s] + g_le[g][e] + ba[0];
    g_ex[g][e] = lg;
    atomicMax(&g_mx[g][d], f2o(lg));
}

// ---------------- exp + denominator ------------------------------------------
__global__ void k_exp(const int* ei1, const int* ei2, int l){
    int g = blockIdx.y;
    int el = blockIdx.x*256 + threadIdx.x;
    if(el >= ELV) return;
    int e = el*LV + l;
    const int* ei = g ? ei2 : ei1;
    int d = ei[EE+e];
    float m = o2f(g_mx[g][d]);
    float ex = __expf(g_ex[g][e] - m);
    g_ex[g][e] = ex;
    atomicAdd(&g_den[g][d], ex);
}

// ---------------- compact receiving nodes ------------------------------------
__global__ void k_compact(){
    int g = blockIdx.y;
    int n = blockIdx.x*256 + threadIdx.x;
    if(n >= NN) return;
    if(g_den[g][n] > 0.f){
        int p = atomicAdd(&g_cnt[g], 1);
        g_list[g][p] = n;
    }
}

// ---------------- message scatter --------------------------------------------
__global__ void k_scatter(const int* ei1, const int* ei2,
                          const float* o1, const float* o2, int l){
    int g = blockIdx.y;
    int el = blockIdx.x*8 + (threadIdx.x>>5);
    if(el >= ELV) return;
    int lane = threadIdx.x & 31;
    int e = el*LV + l;
    const int* ei = g ? ei2 : ei1;
    const float* h = g ? o2 : o1;
    int s = ei[e], d = ei[EE+e];
    float a = g_ex[g][e] / (g_den[g][d] + 1e-16f);
    atomicAdd(&g_msg[g][(size_t)d*DD+lane],    a*h[(size_t)s*DD+lane]);
    atomicAdd(&g_msg[g][(size_t)d*DD+32+lane], a*h[(size_t)s*DD+32+lane]);
}

// ---------------- GRU update GEMM over compacted list ------------------------
// h' = (1-z)*n + z*msg   (GRU hidden state is msg, NOT previous h!)
__global__ __launch_bounds__(256) void k_gru(const float* Whh, const float* bhh,
                                             float* o1, float* o2){
    __shared__ float xs[64*SS];   // msg tile, xs[k][row]
    __shared__ float ws[64*SS];
    __shared__ int   ns[64];
    int g = blockIdx.y;
    int cnt = g_cnt[g];
    int base = blockIdx.x*64;
    if(base >= cnt) return;
    float* h = g ? o2 : o1;
    int t = threadIdx.x;

    #pragma unroll
    for(int i=0;i<4;i++){
        int idx = t + i*256;
        int r = idx>>4, c4 = (idx&15)*4;
        float4 v = make_float4(0.f,0.f,0.f,0.f);
        int node = 0;
        if(base + r < cnt){
            node = g_list[g][base + r];
            v = *(const float4*)&g_msg[g][(size_t)node*DD + c4];
        }
        if(c4 == 0) ns[r] = node;
        xs[(c4+0)*SS + r] = v.x;
        xs[(c4+1)*SS + r] = v.y;
        xs[(c4+2)*SS + r] = v.z;
        xs[(c4+3)*SS + r] = v.w;
    }
    int n0 = (t&15)*4, j0 = (t>>4)*4;
    float acc[3][16];
    #pragma unroll
    for(int p=0;p<3;p++){
        __syncthreads();
        #pragma unroll
        for(int i=0;i<4;i++){
            int idx = t + i*256;
            int r = idx>>4, c4 = (idx&15)*4;
            float4 v = *(const float4*)&Whh[(size_t)(p*64 + r)*DD + c4];
            ws[(c4+0)*SS + r] = v.x;
            ws[(c4+1)*SS + r] = v.y;
            ws[(c4+2)*SS + r] = v.z;
            ws[(c4+3)*SS + r] = v.w;
        }
        __syncthreads();
        #pragma unroll
        for(int q=0;q<16;q++) acc[p][q] = 0.f;
        #pragma unroll 8
        for(int k=0;k<64;k++){
            float4 xv = *(float4*)&xs[k*SS + n0];
            float4 wv = *(float4*)&ws[k*SS + j0];
            acc[p][0] += xv.x*wv.x; acc[p][1] += xv.x*wv.y; acc[p][2] += xv.x*wv.z; acc[p][3] += xv.x*wv.w;
            acc[p][4] += xv.y*wv.x; acc[p][5] += xv.y*wv.y; acc[p][6] += xv.y*wv.z; acc[p][7] += xv.y*wv.w;
            acc[p][8] += xv.z*wv.x; acc[p][9] += xv.z*wv.y; acc[p][10]+= xv.z*wv.z; acc[p][11]+= xv.z*wv.w;
            acc[p][12]+= xv.w*wv.x; acc[p][13]+= xv.w*wv.y; acc[p][14]+= xv.w*wv.z; acc[p][15]+= xv.w*wv.w;
        }
    }
    #pragma unroll
    for(int ni=0;ni<4;ni++){
        int rr = base + n0 + ni;
        if(rr >= cnt) continue;
        int n = ns[n0 + ni];
        float4 gi0 = *(float4*)&g_gi[g][(size_t)n*G3 + j0];
        float4 gi1 = *(float4*)&g_gi[g][(size_t)n*G3 + 64 + j0];
        float4 gi2 = *(float4*)&g_gi[g][(size_t)n*G3 + 128 + j0];
        const float* p0 = (const float*)&gi0;
        const float* p1 = (const float*)&gi1;
        const float* p2 = (const float*)&gi2;
        float hv[4];
        #pragma unroll
        for(int ji=0;ji<4;ji++){
            int d = j0 + ji;
            float msgv = xs[(size_t)d*SS + n0 + ni];   // msg[n][d] from shared tile
            float r  = sigf(p0[ji] + acc[0][ni*4+ji] + __ldg(&bhh[d]));
            float z  = sigf(p1[ji] + acc[1][ni*4+ji] + __ldg(&bhh[64+d]));
            float nn = tanhf(p2[ji] + r*(acc[2][ni*4+ji] + __ldg(&bhh[128+d])));
            hv[ji] = (1.f - z)*nn + z*msgv;
        }
        *(float4*)&h[(size_t)n*DD + j0] = make_float4(hv[0],hv[1],hv[2],hv[3]);
    }
}

// ---------------- leaf cross-combine ------------------------------------------
__global__ void k_leaf(float* o1, float* o2, const float* bc){
    __shared__ float in[128];
    int n = blockIdx.x;       // leaf node id == row id (leaves are [0,NLF))
    int t = threadIdx.x;      // 128
    if(t < 64) in[t] = o1[(size_t)n*DD + t];
    else       in[t] = o2[(size_t)n*DD + t - 64];
    __syncthreads();
    float s = bc[t];
    #pragma unroll 16
    for(int k=0;k<128;k++) s += in[k]*g_WcT[k*128 + t];
    if(t < 64) o1[(size_t)n*DD + t]      = s;
    else       o2[(size_t)n*DD + t - 64] = s;
}

// ---------------- launch -------------------------------------------------------
extern "C" void kernel_launch(void* const* d_in, const int* in_sizes, int n_in,
                              void* d_out, int out_size) {
    const float* x1  = (const float*)d_in[0];
    const int*   ei1 = (const int*)  d_in[1];
    const float* ea1 = (const float*)d_in[2];
    const float* x2  = (const float*)d_in[4];
    const int*   ei2 = (const int*)  d_in[5];
    const float* ea2 = (const float*)d_in[6];
    const float* We  = (const float*)d_in[8];
    const float* be  = (const float*)d_in[9];
    const float* Wa  = (const float*)d_in[10];
    const float* ba  = (const float*)d_in[11];
    const float* Wih = (const float*)d_in[12];
    const float* Whh = (const float*)d_in[13];
    const float* bih = (const float*)d_in[14];
    const float* bhh = (const float*)d_in[15];
    const float* Wc  = (const float*)d_in[16];
    const float* bc  = (const float*)d_in[17];

    float* o1 = (float*)d_out;
    float* o2 = o1 + (size_t)NN*DD;

    k_small<<<1,256>>>(We, Wa, be, Wc);
    k_node_init<<<dim3((NN+7)/8,2),256>>>(x1, x2, Wa);
    k_edge_init<<<dim3((EE+7)/8,2),256>>>(ea1, ea2, ei1, ei2);
    k_gemm_gi<<<dim3((NN+63)/64,2),256>>>(x1, x2, Wih, bih, bhh, o1, o2);

    for(int l=0;l<LV;l++){
        k_prep   <<<dim3((NN+7)/8,2),256>>>(Wa, o1, o2);
        k_logit  <<<dim3((ELV+255)/256,2),256>>>(ei1, ei2, ba, l);
        k_exp    <<<dim3((ELV+255)/256,2),256>>>(ei1, ei2, l);
        k_compact<<<dim3((NN+255)/256,2),256>>>();
        k_scatter<<<dim3((ELV+7)/8,2),256>>>(ei1, ei2, o1, o2, l);
        k_gru    <<<dim3((NN+63)/64,2),256>>>(Whh, bhh, o1, o2);
    }
    k_leaf<<<NLF,128>>>(o1, o2, bc);
}

// round 4
// speedup vs baseline: 1.0392x; 1.0392x over previous
#include <cuda_runtime.h>

#define NN   100000
#define DD   64
#define EE   400000
#define LV   4
#define ELV  (EE/LV)
#define NLF  10000
#define G3   192
#define SX   132   // xs stride (128 rows + pad)
#define SW   196   // ws stride (192 cols + pad)
#define SMEM_BYTES ((64*SX + 64*SW)*4)

// ---------------- scratch (device globals) ----------------------------------
__device__ float g_gi[2][(size_t)NN*G3];   // x@Wih^T + bih
__device__ float g_msg[2][(size_t)NN*DD];  // unnormalized ex-weighted message
__device__ float g_lq[2][NN];              // x . wa_q
__device__ float g_lh[2][NN];              // h . wa_k
__device__ float g_den[2][NN];             // softmax denom, then its inverse
__device__ float g_le[2][EE];              // edge logit term (incl. ba)
__device__ int   g_in[2][NN];              // has incoming edge
__device__ int   g_list[2][NN];            // compacted receiving nodes
__device__ int   g_cnt[2];
__device__ float g_v[DD];                  // We^T wa_k
__device__ float g_c[1];                   // be . wa_k
__device__ float g_WcT[128*128];           // Wc transposed

// ---------------- helpers ----------------------------------------------------
__device__ __forceinline__ float wredsum(float v){
    #pragma unroll
    for(int o=16;o;o>>=1) v += __shfl_down_sync(0xffffffffu, v, o);
    return v;
}
__device__ __forceinline__ float sigf(float x){ return 1.f/(1.f+__expf(-x)); }
__device__ __forceinline__ float tanhsig(float x){ return 2.f*sigf(2.f*x)-1.f; }

// ---------------- tiny precompute ---------------------------------------------
__global__ void k_small(const float* We, const float* Wa, const float* be, const float* Wc){
    int t = threadIdx.x;
    if(t < DD){
        float s = 0.f;
        for(int j=0;j<DD;j++) s += Wa[DD+j]*We[j*DD+t];
        g_v[t] = s;
    }
    if(t == DD){
        float s = 0.f;
        for(int j=0;j<DD;j++) s += be[j]*Wa[DD+j];
        g_c[0] = s;
    }
    for(int i=t;i<128*128;i+=blockDim.x){
        int j=i/128, k=i%128;
        g_WcT[k*128+j] = Wc[i];
    }
}

// ---------------- node init: lq, clear in-flag ---------------------------------
__global__ void k_node_init(const float* x1, const float* x2, const float* Wa){
    int g = blockIdx.y;
    int n = blockIdx.x*8 + (threadIdx.x>>5);
    if(n >= NN) return;
    int lane = threadIdx.x & 31;
    const float* x = g ? x2 : x1;
    float v = x[(size_t)n*DD+lane]*Wa[lane] + x[(size_t)n*DD+32+lane]*Wa[32+lane];
    v = wredsum(v);
    if(lane==0){
        g_lq[g][n] = v;
        g_in[g][n] = 0;
    }
}

// ---------------- edge init: le (incl. ba), incoming flags ----------------------
__global__ void k_edge_init(const float* ea1, const float* ea2,
                            const int* ei1, const int* ei2, const float* ba){
    int g = blockIdx.y;
    int e = blockIdx.x*8 + (threadIdx.x>>5);
    if(e >= EE) return;
    int lane = threadIdx.x & 31;
    const float* ea = g ? ea2 : ea1;
    const int*   ei = g ? ei2 : ei1;
    float v = ea[(size_t)e*DD+lane]*g_v[lane] + ea[(size_t)e*DD+32+lane]*g_v[32+lane];
    v = wredsum(v);
    if(lane==0){
        g_le[g][e] = v + g_c[0] + ba[0];
        g_in[g][ei[EE+e]] = 1;
    }
}

// ---------------- gi GEMM (128x192 tile) + fused root h0 ------------------------
__global__ __launch_bounds__(256,2) void k_gemm_gi(const float* x1, const float* x2,
        const float* Wih, const float* bih, const float* bhh,
        float* o1, float* o2){
    extern __shared__ float sm[];
    float* xs = sm;             // [64][SX] k-major, 128 rows
    float* ws = sm + 64*SX;     // [64][SW] k-major, 192 cols
    int g = blockIdx.y;
    const float* x = g ? x2 : x1;
    float* h = g ? o2 : o1;
    int t = threadIdx.x;
    int base = blockIdx.x*128;

    #pragma unroll
    for(int i=0;i<8;i++){
        int f = t + i*256;
        int r = f>>4, c4 = (f&15)*4;
        int n = base + r;
        float4 v = make_float4(0.f,0.f,0.f,0.f);
        if(n < NN) v = *(const float4*)&x[(size_t)n*DD + c4];
        xs[(c4+0)*SX+r]=v.x; xs[(c4+1)*SX+r]=v.y; xs[(c4+2)*SX+r]=v.z; xs[(c4+3)*SX+r]=v.w;
    }
    #pragma unroll
    for(int i=0;i<12;i++){
        int f = t + i*256;
        int j = f>>4, c4 = (f&15)*4;
        float4 v = *(const float4*)&Wih[(size_t)j*DD + c4];
        ws[(c4+0)*SW+j]=v.x; ws[(c4+1)*SW+j]=v.y; ws[(c4+2)*SW+j]=v.z; ws[(c4+3)*SW+j]=v.w;
    }
    __syncthreads();

    int tx = t>>4, ty = t&15;
    int n0 = tx*8, j0 = ty*4;
    float acc[3][32];
    #pragma unroll
    for(int p=0;p<3;p++)
        #pragma unroll
        for(int q=0;q<32;q++) acc[p][q]=0.f;

    #pragma unroll 4
    for(int k=0;k<64;k++){
        float4 a0 = *(float4*)&xs[k*SX + n0];
        float4 a1 = *(float4*)&xs[k*SX + n0 + 4];
        #pragma unroll
        for(int p=0;p<3;p++){
            float4 w = *(float4*)&ws[k*SW + p*64 + j0];
            float* A = acc[p];
            A[ 0]+=a0.x*w.x; A[ 1]+=a0.x*w.y; A[ 2]+=a0.x*w.z; A[ 3]+=a0.x*w.w;
            A[ 4]+=a0.y*w.x; A[ 5]+=a0.y*w.y; A[ 6]+=a0.y*w.z; A[ 7]+=a0.y*w.w;
            A[ 8]+=a0.z*w.x; A[ 9]+=a0.z*w.y; A[10]+=a0.z*w.z; A[11]+=a0.z*w.w;
            A[12]+=a0.w*w.x; A[13]+=a0.w*w.y; A[14]+=a0.w*w.z; A[15]+=a0.w*w.w;
            A[16]+=a1.x*w.x; A[17]+=a1.x*w.y; A[18]+=a1.x*w.z; A[19]+=a1.x*w.w;
            A[20]+=a1.y*w.x; A[21]+=a1.y*w.y; A[22]+=a1.y*w.z; A[23]+=a1.y*w.w;
            A[24]+=a1.z*w.x; A[25]+=a1.z*w.y; A[26]+=a1.z*w.z; A[27]+=a1.z*w.w;
            A[28]+=a1.w*w.x; A[29]+=a1.w*w.y; A[30]+=a1.w*w.z; A[31]+=a1.w*w.w;
        }
    }

    float4 bi0 = *(const float4*)&bih[j0];
    float4 bi1 = *(const float4*)&bih[64+j0];
    float4 bi2 = *(const float4*)&bih[128+j0];
    float4 bh0 = *(const float4*)&bhh[j0];
    float4 bh1 = *(const float4*)&bhh[64+j0];
    float4 bh2 = *(const float4*)&bhh[128+j0];
    const float* pbi0=(const float*)&bi0; const float* pbi1=(const float*)&bi1; const float* pbi2=(const float*)&bi2;
    const float* pbh0=(const float*)&bh0; const float* pbh1=(const float*)&bh1; const float* pbh2=(const float*)&bh2;

    #pragma unroll
    for(int r=0;r<8;r++){
        int n = base + n0 + r;
        if(n >= NN) continue;
        float gv0[4], gv1[4], gv2[4];
        #pragma unroll
        for(int c=0;c<4;c++){
            gv0[c] = acc[0][r*4+c] + pbi0[c];
            gv1[c] = acc[1][r*4+c] + pbi1[c];
            gv2[c] = acc[2][r*4+c] + pbi2[c];
        }
        *(float4*)&g_gi[g][(size_t)n*G3 +       j0] = make_float4(gv0[0],gv0[1],gv0[2],gv0[3]);
        *(float4*)&g_gi[g][(size_t)n*G3 +  64 + j0] = make_float4(gv1[0],gv1[1],gv1[2],gv1[3]);
        *(float4*)&g_gi[g][(size_t)n*G3 + 128 + j0] = make_float4(gv2[0],gv2[1],gv2[2],gv2[3]);
        bool root = (g_in[g][n] == 0);
        float hv[4];
        #pragma unroll
        for(int c=0;c<4;c++){
            float rr = sigf(gv0[c] + pbh0[c]);
            float zz = sigf(gv1[c] + pbh1[c]);
            float nn = tanhsig(gv2[c] + rr*pbh2[c]);
            hv[c] = root ? (1.f - zz)*nn : 0.f;
        }
        *(float4*)&h[(size_t)n*DD + j0] = make_float4(hv[0],hv[1],hv[2],hv[3]);
    }
}

// ---------------- per-level prep: lh, clear den/msg, reset counters -------------
__global__ void k_prep(const float* Wa, const float* o1, const float* o2){
    if(blockIdx.y==0 && blockIdx.x==0 && threadIdx.x==0){ g_cnt[0]=0; g_cnt[1]=0; }
    int g = blockIdx.y;
    int n = blockIdx.x*8 + (threadIdx.x>>5);
    if(n >= NN) return;
    int lane = threadIdx.x & 31;
    const float* h = g ? o2 : o1;
    float v = h[(size_t)n*DD+lane]*Wa[DD+lane] + h[(size_t)n*DD+32+lane]*Wa[96+lane];
    v = wredsum(v);
    if(lane==0){
        g_lh[g][n] = v;
        g_den[g][n] = 0.f;
    }
    g_msg[g][(size_t)n*DD+lane]    = 0.f;
    g_msg[g][(size_t)n*DD+32+lane] = 0.f;
}

// ---------------- fused: logit -> exp -> den red -> msg red (one edge pass) -----
__global__ void k_scatter(const int* ei1, const int* ei2,
                          const float* o1, const float* o2, int l){
    int g = blockIdx.y;
    int t = threadIdx.x;
    int lane = t & 31;
    int sl = lane & 15, h2 = lane >> 4;
    int ew = (blockIdx.x*8 + (t>>5))*2 + h2;   // 16 edges per 256-thread block
    if(ew >= ELV) return;
    int e = ew*LV + l;
    const int* ei = g ? ei2 : ei1;
    const float* h = g ? o2 : o1;
    int s = ei[e], d = ei[EE+e];
    float ex = __expf(g_lq[g][d] + g_lh[g][s] + g_le[g][e]);  // shift-free softmax
    if(sl == 0) atomicAdd(&g_den[g][d], ex);
    float4 hv = *(const float4*)&h[(size_t)s*DD + sl*4];
    float4 m = make_float4(ex*hv.x, ex*hv.y, ex*hv.z, ex*hv.w);
    float* p = &g_msg[g][(size_t)d*DD + sl*4];
    asm volatile("red.global.add.v4.f32 [%0], {%1,%2,%3,%4};"
                 :: "l"(p), "f"(m.x), "f"(m.y), "f"(m.z), "f"(m.w) : "memory");
}

// ---------------- compact receiving nodes + invert den ---------------------------
__global__ void k_compact(){
    int g = blockIdx.y;
    int n = blockIdx.x*256 + threadIdx.x;
    if(n >= NN) return;
    float d = g_den[g][n];
    if(d > 0.f){
        int p = atomicAdd(&g_cnt[g], 1);
        g_list[g][p] = n;
        g_den[g][n] = 1.f/(d + 1e-16f);
    }
}

// ---------------- GRU update GEMM over compacted list (128x192 tile) -------------
// h' = (1-z)*n + z*msg   (GRU "hidden" is msg)
__global__ __launch_bounds__(256,2) void k_gru(const float* Whh, const float* bhh,
                                               float* o1, float* o2){
    extern __shared__ float sm[];
    float* xs = sm;             // normalized msg tile, k-major
    float* ws = sm + 64*SX;
    __shared__ int ns[128];
    int g = blockIdx.y;
    int cnt = g_cnt[g];
    int base = blockIdx.x*128;
    if(base >= cnt) return;
    float* h = g ? o2 : o1;
    int t = threadIdx.x;

    #pragma unroll
    for(int i=0;i<8;i++){
        int f = t + i*256;
        int r = f>>4, c4 = (f&15)*4;
        int rr = base + r;
        float4 v = make_float4(0.f,0.f,0.f,0.f);
        int node = 0;
        if(rr < cnt){
            node = g_list[g][rr];
            float dv = g_den[g][node];   // inverse denom
            float4 m = *(const float4*)&g_msg[g][(size_t)node*DD + c4];
            v = make_float4(m.x*dv, m.y*dv, m.z*dv, m.w*dv);
        }
        if(c4 == 0) ns[r] = node;
        xs[(c4+0)*SX+r]=v.x; xs[(c4+1)*SX+r]=v.y; xs[(c4+2)*SX+r]=v.z; xs[(c4+3)*SX+r]=v.w;
    }
    #pragma unroll
    for(int i=0;i<12;i++){
        int f = t + i*256;
        int j = f>>4, c4 = (f&15)*4;
        float4 v = *(const float4*)&Whh[(size_t)j*DD + c4];
        ws[(c4+0)*SW+j]=v.x; ws[(c4+1)*SW+j]=v.y; ws[(c4+2)*SW+j]=v.z; ws[(c4+3)*SW+j]=v.w;
    }
    __syncthreads();

    int tx = t>>4, ty = t&15;
    int n0 = tx*8, j0 = ty*4;
    float acc[3][32];
    #pragma unroll
    for(int p=0;p<3;p++)
        #pragma unroll
        for(int q=0;q<32;q++) acc[p][q]=0.f;

    #pragma unroll 4
    for(int k=0;k<64;k++){
        float4 a0 = *(float4*)&xs[k*SX + n0];
        float4 a1 = *(float4*)&xs[k*SX + n0 + 4];
        #pragma unroll
        for(int p=0;p<3;p++){
            float4 w = *(float4*)&ws[k*SW + p*64 + j0];
            float* A = acc[p];
            A[ 0]+=a0.x*w.x; A[ 1]+=a0.x*w.y; A[ 2]+=a0.x*w.z; A[ 3]+=a0.x*w.w;
            A[ 4]+=a0.y*w.x; A[ 5]+=a0.y*w.y; A[ 6]+=a0.y*w.z; A[ 7]+=a0.y*w.w;
            A[ 8]+=a0.z*w.x; A[ 9]+=a0.z*w.y; A[10]+=a0.z*w.z; A[11]+=a0.z*w.w;
            A[12]+=a0.w*w.x; A[13]+=a0.w*w.y; A[14]+=a0.w*w.z; A[15]+=a0.w*w.w;
            A[16]+=a1.x*w.x; A[17]+=a1.x*w.y; A[18]+=a1.x*w.z; A[19]+=a1.x*w.w;
            A[20]+=a1.y*w.x; A[21]+=a1.y*w.y; A[22]+=a1.y*w.z; A[23]+=a1.y*w.w;
            A[24]+=a1.z*w.x; A[25]+=a1.z*w.y; A[26]+=a1.z*w.z; A[27]+=a1.z*w.w;
            A[28]+=a1.w*w.x; A[29]+=a1.w*w.y; A[30]+=a1.w*w.z; A[31]+=a1.w*w.w;
        }
    }

    float4 bh0 = *(const float4*)&bhh[j0];
    float4 bh1 = *(const float4*)&bhh[64+j0];
    float4 bh2 = *(const float4*)&bhh[128+j0];
    const float* pbh0=(const float*)&bh0; const float* pbh1=(const float*)&bh1; const float* pbh2=(const float*)&bh2;

    #pragma unroll
    for(int r=0;r<8;r++){
        int rr = base + n0 + r;
        if(rr >= cnt) continue;
        int n = ns[n0 + r];
        float4 gi0 = *(float4*)&g_gi[g][(size_t)n*G3 +       j0];
        float4 gi1 = *(float4*)&g_gi[g][(size_t)n*G3 +  64 + j0];
        float4 gi2 = *(float4*)&g_gi[g][(size_t)n*G3 + 128 + j0];
        const float* p0=(const float*)&gi0; const float* p1=(const float*)&gi1; const float* p2=(const float*)&gi2;
        float hv[4];
        #pragma unroll
        for(int c=0;c<4;c++){
            float msgv = xs[(j0+c)*SX + n0 + r];
            float rg = sigf(p0[c] + acc[0][r*4+c] + pbh0[c]);
            float zg = sigf(p1[c] + acc[1][r*4+c] + pbh1[c]);
            float ng = tanhsig(p2[c] + rg*(acc[2][r*4+c] + pbh2[c]));
            hv[c] = (1.f - zg)*ng + zg*msgv;
        }
        *(float4*)&h[(size_t)n*DD + j0] = make_float4(hv[0],hv[1],hv[2],hv[3]);
    }
}

// ---------------- leaf cross-combine (batched, WcT reuse) -------------------------
__global__ __launch_bounds__(128) void k_leaf(float* o1, float* o2, const float* bc){
    __shared__ float in[16*130];
    int lb = blockIdx.x*16;
    int t = threadIdx.x;
    #pragma unroll
    for(int i=0;i<16;i++){
        int n = lb + i;
        if(t < 64) in[i*130+t] = o1[(size_t)n*DD + t];
        else       in[i*130+t] = o2[(size_t)n*DD + t - 64];
    }
    __syncthreads();
    float acc[16];
    float b = bc[t];
    #pragma unroll
    for(int i=0;i<16;i++) acc[i] = b;
    #pragma unroll 4
    for(int k=0;k<128;k++){
        float w = g_WcT[k*128 + t];
        #pragma unroll
        for(int i=0;i<16;i++) acc[i] += in[i*130+k]*w;
    }
    #pragma unroll
    for(int i=0;i<16;i++){
        int n = lb + i;
        if(t < 64) o1[(size_t)n*DD + t]      = acc[i];
        else       o2[(size_t)n*DD + t - 64] = acc[i];
    }
}

// ---------------- launch -----------------------------------------------------------
extern "C" void kernel_launch(void* const* d_in, const int* in_sizes, int n_in,
                              void* d_out, int out_size) {
    const float* x1  = (const float*)d_in[0];
    const int*   ei1 = (const int*)  d_in[1];
    const float* ea1 = (const float*)d_in[2];
    const float* x2  = (const float*)d_in[4];
    const int*   ei2 = (const int*)  d_in[5];
    const float* ea2 = (const float*)d_in[6];
    const float* We  = (const float*)d_in[8];
    const float* be  = (const float*)d_in[9];
    const float* Wa  = (const float*)d_in[10];
    const float* ba  = (const float*)d_in[11];
    const float* Wih = (const float*)d_in[12];
    const float* Whh = (const float*)d_in[13];
    const float* bih = (const float*)d_in[14];
    const float* bhh = (const float*)d_in[15];
    const float* Wc  = (const float*)d_in[16];
    const float* bc  = (const float*)d_in[17];

    float* o1 = (float*)d_out;
    float* o2 = o1 + (size_t)NN*DD;

    cudaFuncSetAttribute(k_gemm_gi, cudaFuncAttributeMaxDynamicSharedMemorySize, SMEM_BYTES);
    cudaFuncSetAttribute(k_gru,     cudaFuncAttributeMaxDynamicSharedMemorySize, SMEM_BYTES);

    k_small<<<1,256>>>(We, Wa, be, Wc);
    k_node_init<<<dim3((NN+7)/8,2),256>>>(x1, x2, Wa);
    k_edge_init<<<dim3((EE+7)/8,2),256>>>(ea1, ea2, ei1, ei2, ba);
    k_gemm_gi<<<dim3((NN+127)/128,2),256,SMEM_BYTES>>>(x1, x2, Wih, bih, bhh, o1, o2);

    for(int l=0;l<LV;l++){
        k_prep   <<<dim3((NN+7)/8,2),256>>>(Wa, o1, o2);
        k_scatter<<<dim3((ELV+15)/16,2),256>>>(ei1, ei2, o1, o2, l);
        k_compact<<<dim3((NN+255)/256,2),256>>>();
        k_gru    <<<dim3((NN+127)/128,2),256,SMEM_BYTES>>>(Whh, bhh, o1, o2);
    }
    k_leaf<<<NLF/16,128>>>(o1, o2, bc);
}